// round 1
// baseline (speedup 1.0000x reference)
#include <cuda_runtime.h>

// ALNNLayer fused kernel.
// Shapes: X,T,M,DT: [B=64, L=200, D=64]; alpha: [K=13]; w_v,b_t: [K,L,D];
//         w_t: [K,L,D,4]; b_v: [K,1,D]; out: [B,K,D].
// Math per (b,k,l,d):
//   dist  = |T - 4k|
//   kern  = exp(-relu(alpha_k) * dist)
//   inten = relu(X * kern)
//   lat   = relu(wt0*X + wt1*DT + wt2*inten + wt3*M + 4*b_t)   (b_t broadcast over 4 feats)
//   out[b,k,d] = relu( sum_l w_v*lat + 200*b_v[k,d] )          (b_v broadcast over L)

#define KREF 13
#define LN   200
#define DN   64
#define BN   64

__global__ __launch_bounds__(256, 8)
void alnn_kernel(const float* __restrict__ X,
                 const float* __restrict__ T,
                 const float* __restrict__ M,
                 const float* __restrict__ DT,
                 const float* __restrict__ alpha,
                 const float* __restrict__ w_v,
                 const float* __restrict__ w_t,
                 const float* __restrict__ b_v,
                 const float* __restrict__ b_t,
                 float* __restrict__ out)
{
    const int bx  = blockIdx.x;          // b*K + k
    const int b   = bx / KREF;
    const int k   = bx - b * KREF;
    const int tid = threadIdx.x;
    const int lg  = tid >> 5;            // l-group 0..7
    const int d0  = (tid & 31) * 2;      // d pair base

    const float a  = fmaxf(__ldg(alpha + k), 0.0f);   // relu(alpha_k)
    const float rt = 4.0f * (float)k;                 // linspace(0,48,13)[k]

    const float* __restrict__ Xb   = X   + b * (LN * DN) + d0;
    const float* __restrict__ Tb   = T   + b * (LN * DN) + d0;
    const float* __restrict__ Mb   = M   + b * (LN * DN) + d0;
    const float* __restrict__ DTb  = DT  + b * (LN * DN) + d0;
    const float* __restrict__ wvk  = w_v + k * (LN * DN) + d0;
    const float* __restrict__ btk  = b_t + k * (LN * DN) + d0;
    const float* __restrict__ wtk  = w_t + (size_t)(k * (LN * DN) + d0) * 4;

    float acc0 = 0.0f, acc1 = 0.0f;

    #pragma unroll 5
    for (int l = lg; l < LN; l += 8) {
        const int off = l * DN;
        const float2 x  = *reinterpret_cast<const float2*>(Xb  + off);
        const float2 t  = *reinterpret_cast<const float2*>(Tb  + off);
        const float2 m  = *reinterpret_cast<const float2*>(Mb  + off);
        const float2 dt = *reinterpret_cast<const float2*>(DTb + off);
        const float2 wv = *reinterpret_cast<const float2*>(wvk + off);
        const float2 bt = *reinterpret_cast<const float2*>(btk + off);
        const float4 wt0 = *reinterpret_cast<const float4*>(wtk + (size_t)off * 4);
        const float4 wt1 = *reinterpret_cast<const float4*>(wtk + (size_t)off * 4 + 4);

        const float kern0 = __expf(-a * fabsf(t.x - rt));
        const float kern1 = __expf(-a * fabsf(t.y - rt));
        const float in0   = fmaxf(x.x * kern0, 0.0f);
        const float in1   = fmaxf(x.y * kern1, 0.0f);

        float s0 = fmaf(wt0.x, x.x,
                   fmaf(wt0.y, dt.x,
                   fmaf(wt0.z, in0,
                   fmaf(wt0.w, m.x, 4.0f * bt.x))));
        float s1 = fmaf(wt1.x, x.y,
                   fmaf(wt1.y, dt.y,
                   fmaf(wt1.z, in1,
                   fmaf(wt1.w, m.y, 4.0f * bt.y))));

        acc0 = fmaf(wv.x, fmaxf(s0, 0.0f), acc0);
        acc1 = fmaf(wv.y, fmaxf(s1, 0.0f), acc1);
    }

    // Reduce the 8 l-group partials per d.
    __shared__ float red[8][DN];
    red[lg][d0]     = acc0;
    red[lg][d0 + 1] = acc1;
    __syncthreads();

    if (tid < DN) {
        float s = 0.0f;
        #pragma unroll
        for (int i = 0; i < 8; i++) s += red[i][tid];
        const float bv = __ldg(b_v + k * DN + tid);
        out[(b * KREF + k) * DN + tid] = fmaxf(fmaf(200.0f, bv, s), 0.0f);
    }
}

extern "C" void kernel_launch(void* const* d_in, const int* in_sizes, int n_in,
                              void* d_out, int out_size)
{
    // metadata order: X, T, M, DT, alpha, w_v, w_t, b_v, b_t
    const float* X     = (const float*)d_in[0];
    const float* T     = (const float*)d_in[1];
    const float* M     = (const float*)d_in[2];
    const float* DT    = (const float*)d_in[3];
    const float* alpha = (const float*)d_in[4];
    const float* w_v   = (const float*)d_in[5];
    const float* w_t   = (const float*)d_in[6];
    const float* b_v   = (const float*)d_in[7];
    const float* b_t   = (const float*)d_in[8];
    float* out = (float*)d_out;

    alnn_kernel<<<BN * KREF, 256>>>(X, T, M, DT, alpha, w_v, w_t, b_v, b_t, out);
}

// round 2
// speedup vs baseline: 1.0440x; 1.0440x over previous
#include <cuda_runtime.h>

// ALNNLayer fused kernel, 2-D tiled: block = (b-tile of 8) x (all K=13) x (l-chunk of 5).
// Shapes: X,T,M,DT: [B=64, L=200, D=64]; alpha: [K=13]; w_v,b_t: [K,L,D];
//         w_t: [K,L,D,4]; b_v: [K,1,D]; out: [B,K,D].
// Per (b,k,l,d):
//   kern  = exp(-relu(alpha_k) * |T - 4k|)
//   inten = kern * relu(X)
//   lat   = relu(wt0*X + wt1*DT + wt2*inten + wt3*M + 4*b_t)
//   out[b,k,d] = relu( sum_l w_v*lat + 200*b_v[k,d] )

#define KREF 13
#define LN   200
#define DN   64
#define BN   64
#define BT   8           // b-tile per block
#define LC   5           // l-steps per block
#define NCHUNK (LN / LC) // 40
#define NBT    (BN / BT) // 8

// scratch[chunk][b][k][d]
__device__ float g_scratch[NCHUNK * BN * KREF * DN];

__global__ __launch_bounds__(416, 2)
void alnn_main(const float* __restrict__ X,
               const float* __restrict__ T,
               const float* __restrict__ M,
               const float* __restrict__ DT,
               const float* __restrict__ alpha,
               const float* __restrict__ w_v,
               const float* __restrict__ w_t,
               const float* __restrict__ b_t)
{
    const int chunk = blockIdx.x;        // 0..39
    const int btile = blockIdx.y;        // 0..7
    const int tid   = threadIdx.x;
    const int k     = tid >> 5;          // warp id = k (0..12)
    const int lane  = tid & 31;
    const int d0    = lane * 2;

    const float a  = fmaxf(__ldg(alpha + k), 0.0f);
    const float rt = 4.0f * (float)k;
    const int   l0 = chunk * LC;
    const int   b0 = btile * BT;

    float accx[BT], accy[BT];
    #pragma unroll
    for (int i = 0; i < BT; i++) { accx[i] = 0.0f; accy[i] = 0.0f; }

    for (int li = 0; li < LC; li++) {
        const int l  = l0 + li;
        const int wk = (k * LN + l) * DN + d0;

        const float2 wv = *reinterpret_cast<const float2*>(w_v + wk);
        const float2 bt = *reinterpret_cast<const float2*>(b_t + wk);
        const float4 wt0 = *reinterpret_cast<const float4*>(w_t + (size_t)wk * 4);
        const float4 wt1 = *reinterpret_cast<const float4*>(w_t + (size_t)wk * 4 + 4);
        const float bt4x = 4.0f * bt.x;
        const float bt4y = 4.0f * bt.y;

        #pragma unroll
        for (int bi = 0; bi < BT; bi++) {
            const int off = ((b0 + bi) * LN + l) * DN + d0;
            const float2 x  = *reinterpret_cast<const float2*>(X  + off);
            const float2 t  = *reinterpret_cast<const float2*>(T  + off);
            const float2 m  = *reinterpret_cast<const float2*>(M  + off);
            const float2 dt = *reinterpret_cast<const float2*>(DT + off);

            const float in0 = __expf(-a * fabsf(t.x - rt)) * fmaxf(x.x, 0.0f);
            const float in1 = __expf(-a * fabsf(t.y - rt)) * fmaxf(x.y, 0.0f);

            float s0 = fmaf(wt0.x, x.x,
                       fmaf(wt0.y, dt.x,
                       fmaf(wt0.z, in0,
                       fmaf(wt0.w, m.x, bt4x))));
            float s1 = fmaf(wt1.x, x.y,
                       fmaf(wt1.y, dt.y,
                       fmaf(wt1.z, in1,
                       fmaf(wt1.w, m.y, bt4y))));

            accx[bi] = fmaf(wv.x, fmaxf(s0, 0.0f), accx[bi]);
            accy[bi] = fmaf(wv.y, fmaxf(s1, 0.0f), accy[bi]);
        }
    }

    // scratch[chunk][b][k][d]
    #pragma unroll
    for (int bi = 0; bi < BT; bi++) {
        float2 v = make_float2(accx[bi], accy[bi]);
        *reinterpret_cast<float2*>(
            g_scratch + ((size_t)(chunk * BN + b0 + bi) * KREF + k) * DN + d0) = v;
    }
}

__global__ __launch_bounds__(256)
void alnn_finalize(const float* __restrict__ b_v, float* __restrict__ out)
{
    const int idx = blockIdx.x * 256 + threadIdx.x;   // over B*K*D = 53248
    if (idx >= BN * KREF * DN) return;
    const int d  = idx & (DN - 1);
    const int k  = (idx / DN) % KREF;

    float s = 0.0f;
    #pragma unroll
    for (int c = 0; c < NCHUNK; c++)
        s += g_scratch[(size_t)c * (BN * KREF * DN) + idx];

    const float bv = __ldg(b_v + k * DN + d);
    out[idx] = fmaxf(fmaf(200.0f, bv, s), 0.0f);
}

extern "C" void kernel_launch(void* const* d_in, const int* in_sizes, int n_in,
                              void* d_out, int out_size)
{
    // metadata order: X, T, M, DT, alpha, w_v, w_t, b_v, b_t
    const float* X     = (const float*)d_in[0];
    const float* T     = (const float*)d_in[1];
    const float* M     = (const float*)d_in[2];
    const float* DT    = (const float*)d_in[3];
    const float* alpha = (const float*)d_in[4];
    const float* w_v   = (const float*)d_in[5];
    const float* w_t   = (const float*)d_in[6];
    const float* b_v   = (const float*)d_in[7];
    const float* b_t   = (const float*)d_in[8];
    float* out = (float*)d_out;

    dim3 grid(NCHUNK, NBT);
    alnn_main<<<grid, 416>>>(X, T, M, DT, alpha, w_v, w_t, b_t);
    alnn_finalize<<<(BN * KREF * DN + 255) / 256, 256>>>(b_v, out);
}